// round 4
// baseline (speedup 1.0000x reference)
#include <cuda_runtime.h>
#include <cmath>

#define WLEN  512
#define SEG   16
#define VCOLS 16
#define VSTR  514   // column stride in vertical tile; 514 % 32 == 2 -> conflict-free staging

// Scratch (device globals: allocation-free rule)
__device__ float g_buf[4 * 32 * 512 * 512];   // 128 MB intermediate
__device__ float g_V1[4 * 512 * 512];         // exp(cc0 * D)
__device__ float g_V2[4 * 512 * 512];         // V1^2

__device__ __forceinline__ int SWZ(int w) { return w ^ (w >> 5); }

// ---------------------------------------------------------------------------
// Register-resident forward+backward scan over one 512-line.
// Lane l owns elements [16l, 16l+16) in x[]; v[] holds the matching V
// (v[0] of lane 0 must already be 0). On return x[] holds the filtered line.
__device__ __forceinline__ void scan_regs(float x[SEG], float v[SEG], int lane) {
    const unsigned M = 0xffffffffu;

    // ---- forward: x_i = v_i*x_{i-1} + (1-v_i)*e_i, x_{-1} = 0
    float A = 1.f, B = 0.f;
#pragma unroll
    for (int j = 0; j < SEG; ++j) { B = fmaf(v[j], B - x[j], x[j]); A *= v[j]; }
    // inclusive prefix compose (left neighbor applied first)
#pragma unroll
    for (int d = 1; d < 32; d <<= 1) {
        float Au = __shfl_up_sync(M, A, d);
        float Bu = __shfl_up_sync(M, B, d);
        if (lane >= d) { B = fmaf(A, Bu, B); A *= Au; }
    }
    float cf = __shfl_up_sync(M, B, 1);
    float xx = (lane == 0) ? 0.f : cf;
#pragma unroll
    for (int j = 0; j < SEG; ++j) { xx = fmaf(v[j], xx - x[j], x[j]); x[j] = xx; }

    // ---- backward: y_i = w_i*y_{i+1} + (1-w_i)*x_i, w_i = v_{i+1}, w_511 = 0
    float w15 = __shfl_down_sync(M, v[0], 1);   // next lane's v[0] = v at 16l+16
    if (lane == 31) w15 = 0.f;
    A = 1.f; B = 0.f;
#pragma unroll
    for (int j = SEG - 1; j >= 0; --j) {
        float w = (j == SEG - 1) ? w15 : v[j + 1];
        B = fmaf(w, B - x[j], x[j]); A *= w;
    }
    // inclusive suffix compose (right neighbor applied first)
#pragma unroll
    for (int d = 1; d < 32; d <<= 1) {
        float Ad = __shfl_down_sync(M, A, d);
        float Bd = __shfl_down_sync(M, B, d);
        if (lane + d < 32) { B = fmaf(A, Bd, B); A *= Ad; }
    }
    float cb = __shfl_down_sync(M, B, 1);
    float yy = (lane == 31) ? 0.f : cb;
#pragma unroll
    for (int j = SEG - 1; j >= 0; --j) {
        float w = (j == SEG - 1) ? w15 : v[j + 1];
        yy = fmaf(w, yy - x[j], x[j]);
        x[j] = yy;
    }
}

// ---------------------------------------------------------------------------
// V precompute: V1 = exp(cc0 * (1 + 150*edge)), V2 = V1^2  (sigma0 = 2*sigma1)
__global__ void __launch_bounds__(1024) vprep(const float* __restrict__ edge,
                                              float cc0, int n) {
    int i = blockIdx.x * blockDim.x + threadIdx.x;
    if (i < n) {
        float D  = fmaf(150.f, edge[i], 1.f);
        float v1 = expf(cc0 * D);
        g_V1[i] = v1;
        g_V2[i] = v1 * v1;
    }
}

// ---------------------------------------------------------------------------
// Horizontal pass: pure register kernel, no smem. Warp = one (b,ch,h) line.
// Lane l loads its 16-element segment with 4x LDG.128, scans, 4x STG.128.
__global__ void __launch_bounds__(256) dt_h(const float* __restrict__ src,
                                            float* __restrict__ dst,
                                            const float* __restrict__ Vg) {
    int t = threadIdx.x, lane = t & 31, warp = t >> 5;
    int cg = blockIdx.x & 3;             // channel group (4 blocks share one V row)
    int h  = (blockIdx.x >> 2) & 511;
    int b  = blockIdx.x >> 11;
    int ch = cg * 8 + warp;

    size_t base = (((size_t)b * 32 + ch) * 512 + h) * 512;
    const float4* s4 = reinterpret_cast<const float4*>(src + base);
    const float4* v4 = reinterpret_cast<const float4*>(Vg + ((size_t)b * 512 + h) * 512);

    float x[SEG], v[SEG];
#pragma unroll
    for (int q = 0; q < 4; ++q) {
        float4 d = s4[4 * lane + q];
        x[4 * q + 0] = d.x; x[4 * q + 1] = d.y; x[4 * q + 2] = d.z; x[4 * q + 3] = d.w;
        float4 vv = v4[4 * lane + q];
        v[4 * q + 0] = vv.x; v[4 * q + 1] = vv.y; v[4 * q + 2] = vv.z; v[4 * q + 3] = vv.w;
    }
    if (lane == 0) v[0] = 0.f;           // boundary: a_0 = 0

    scan_regs(x, v, lane);

    float4* d4 = reinterpret_cast<float4*>(dst + base);
#pragma unroll
    for (int q = 0; q < 4; ++q) {
        float4 o;
        o.x = x[4 * q + 0]; o.y = x[4 * q + 1]; o.z = x[4 * q + 2]; o.w = x[4 * q + 3];
        d4[4 * lane + q] = o;
    }
}

// ---------------------------------------------------------------------------
// Vertical pass: block = (b, c, 16-column group), 16 warps = 16 columns.
// smem only for the transpose; the scan itself runs in registers.
__global__ void __launch_bounds__(512) dt_v(const float* __restrict__ src,
                                            float* __restrict__ dst,
                                            const float* __restrict__ Vg) {
    extern __shared__ float sm[];
    float* timg = sm;                  // 16 * 514
    float* tv   = sm + VCOLS * VSTR;   // 16 * 514

    int t = threadIdx.x, lane = t & 31, warp = t >> 5;
    int wg = blockIdx.x & 31, c = (blockIdx.x >> 5) & 31, b = blockIdx.x >> 10;
    int w0 = wg * VCOLS;
    int f = t & 3, row = t >> 2;       // f: float4 slot along w, row: h sub-row (0..127)

    const float* sbase = src + (((size_t)b * 32 + c) * 512) * 512 + w0;
    const float* vbase = Vg + ((size_t)b * 512) * 512 + w0;

#pragma unroll
    for (int k = 0; k < 4; ++k) {
        int h = k * 128 + row;
        float4 d  = *reinterpret_cast<const float4*>(sbase + (size_t)h * 512 + f * 4);
        float4 vv = *reinterpret_cast<const float4*>(vbase + (size_t)h * 512 + f * 4);
        if (h == 0) { vv.x = 0.f; vv.y = 0.f; vv.z = 0.f; vv.w = 0.f; }
        int s = SWZ(h);
        int col = f * 4;
        timg[(col    ) * VSTR + s] = d.x;
        timg[(col + 1) * VSTR + s] = d.y;
        timg[(col + 2) * VSTR + s] = d.z;
        timg[(col + 3) * VSTR + s] = d.w;
        tv  [(col    ) * VSTR + s] = vv.x;
        tv  [(col + 1) * VSTR + s] = vv.y;
        tv  [(col + 2) * VSTR + s] = vv.z;
        tv  [(col + 3) * VSTR + s] = vv.w;
    }
    __syncthreads();

    // register scan: lane l of warp c owns h = [16l, 16l+16) of column c
    {
        float* colp = timg + warp * VSTR;
        float* vcol = tv   + warp * VSTR;
        float x[SEG], v[SEG];
#pragma unroll
        for (int j = 0; j < SEG; ++j) {
            int s = SWZ(SEG * lane + j);
            x[j] = colp[s];
            v[j] = vcol[s];
        }
        scan_regs(x, v, lane);
#pragma unroll
        for (int j = 0; j < SEG; ++j) colp[SWZ(SEG * lane + j)] = x[j];
    }
    __syncthreads();

    float* dbase = dst + (((size_t)b * 32 + c) * 512) * 512 + w0;
#pragma unroll
    for (int k = 0; k < 4; ++k) {
        int h = k * 128 + row;
        int s = SWZ(h);
        int col = f * 4;
        float4 o;
        o.x = timg[(col    ) * VSTR + s];
        o.y = timg[(col + 1) * VSTR + s];
        o.z = timg[(col + 2) * VSTR + s];
        o.w = timg[(col + 3) * VSTR + s];
        *reinterpret_cast<float4*>(dbase + (size_t)h * 512 + f * 4) = o;
    }
}

// ---------------------------------------------------------------------------
extern "C" void kernel_launch(void* const* d_in, const int* in_sizes, int n_in,
                              void* d_out, int out_size) {
    const float* img  = (const float*)d_in[0];
    const float* edge = (const float*)d_in[1];
    // defensive: identify by size (img = 33.5M, edge = 1M)
    if (n_in >= 2 && in_sizes[0] == (1 << 20)) {
        const float* tmp = img; img = edge; edge = tmp;
    }
    float* out = (float*)d_out;

    float *buf, *V1, *V2;
    cudaGetSymbolAddress((void**)&buf, g_buf);
    cudaGetSymbolAddress((void**)&V1, g_V1);
    cudaGetSymbolAddress((void**)&V2, g_V2);

    const int SMEM_V = 2 * VCOLS * VSTR * (int)sizeof(float);       // 65792 B
    cudaFuncSetAttribute(dt_v, cudaFuncAttributeMaxDynamicSharedMemorySize, SMEM_V);

    // sigma_0 = 60*sqrt(3)*2/sqrt(15);  cc0 = -sqrt(2)/sigma_0;  sigma_1 = sigma_0/2
    double sigma0 = 60.0 * 1.7320508075688772 * 2.0 / sqrt(15.0);
    float cc0 = (float)(-1.4142135623730951 / sigma0);

    vprep<<<1024, 1024>>>(edge, cc0, 1 << 20);
    dt_h<<<8192, 256>>>(img, buf, V1);            // iter 0, horizontal
    dt_v<<<4096, 512, SMEM_V>>>(buf, buf, V1);    // iter 0, vertical (in place)
    dt_h<<<8192, 256>>>(buf, buf, V2);            // iter 1, horizontal (in place)
    dt_v<<<4096, 512, SMEM_V>>>(buf, out, V2);    // iter 1, vertical -> output
}

// round 11
// speedup vs baseline: 1.2552x; 1.2552x over previous
#include <cuda_runtime.h>
#include <cmath>

#define WLEN  512
#define SEG   16
#define VCOLS 16
#define VSTR  514   // vertical tile column stride; 514 % 32 == 2 -> conflict-free staging

// Scratch (device globals: allocation-free rule)
__device__ float g_buf[4 * 32 * 512 * 512];   // 128 MB intermediate
__device__ float g_V1[4 * 512 * 512];         // exp(cc0 * D)
__device__ float g_V2[4 * 512 * 512];         // V1^2

__device__ __forceinline__ int SWZ(int w) { return w ^ (w >> 5); }

// ---------------------------------------------------------------------------
// Register-resident forward+backward scan over one 512-line.
// Lane l owns elements [16l, 16l+16) in x[]; v[] holds matching V
// (lane 0's v[0] must already be 0). On return x[] holds the filtered line.
__device__ __forceinline__ void scan_regs(float x[SEG], float v[SEG], int lane) {
    const unsigned M = 0xffffffffu;

    // ---- forward: x_i = v_i*x_{i-1} + (1-v_i)*e_i, x_{-1} = 0
    float A = 1.f, B = 0.f;
#pragma unroll
    for (int j = 0; j < SEG; ++j) { B = fmaf(v[j], B - x[j], x[j]); A *= v[j]; }
#pragma unroll
    for (int d = 1; d < 32; d <<= 1) {
        float Au = __shfl_up_sync(M, A, d);
        float Bu = __shfl_up_sync(M, B, d);
        if (lane >= d) { B = fmaf(A, Bu, B); A *= Au; }
    }
    float cf = __shfl_up_sync(M, B, 1);
    float xx = (lane == 0) ? 0.f : cf;
#pragma unroll
    for (int j = 0; j < SEG; ++j) { xx = fmaf(v[j], xx - x[j], x[j]); x[j] = xx; }

    // ---- backward: y_i = w_i*y_{i+1} + (1-w_i)*x_i, w_i = v_{i+1}, w_511 = 0
    float w15 = __shfl_down_sync(M, v[0], 1);   // next lane's v[0] = V at 16l+16
    if (lane == 31) w15 = 0.f;
    A = 1.f; B = 0.f;
#pragma unroll
    for (int j = SEG - 1; j >= 0; --j) {
        float w = (j == SEG - 1) ? w15 : v[j + 1];
        B = fmaf(w, B - x[j], x[j]); A *= w;
    }
#pragma unroll
    for (int d = 1; d < 32; d <<= 1) {
        float Ad = __shfl_down_sync(M, A, d);
        float Bd = __shfl_down_sync(M, B, d);
        if (lane + d < 32) { B = fmaf(A, Bd, B); A *= Ad; }
    }
    float cb = __shfl_down_sync(M, B, 1);
    float yy = (lane == 31) ? 0.f : cb;
#pragma unroll
    for (int j = SEG - 1; j >= 0; --j) {
        float w = (j == SEG - 1) ? w15 : v[j + 1];
        yy = fmaf(w, yy - x[j], x[j]);
        x[j] = yy;
    }
}

// ---------------------------------------------------------------------------
// Smem-resident forward+backward scan (for the vertical pass, R3-proven).
// One warp per line; vs[SWZ(0)] must be 0.
__device__ __forceinline__ void scan_line(float* xs, const float* vs, int lane) {
    float A = 1.f, B = 0.f;
#pragma unroll
    for (int j = 0; j < SEG; ++j) {
        int w = lane * SEG + j;
        float v = vs[SWZ(w)];
        float e = xs[SWZ(w)];
        B = fmaf(v, B - e, e);
        A *= v;
    }
#pragma unroll
    for (int d = 1; d < 32; d <<= 1) {
        float Au = __shfl_up_sync(0xffffffffu, A, d);
        float Bu = __shfl_up_sync(0xffffffffu, B, d);
        if (lane >= d) { B = fmaf(A, Bu, B); A *= Au; }
    }
    float c = __shfl_up_sync(0xffffffffu, B, 1);
    float x = (lane == 0) ? 0.f : c;
#pragma unroll
    for (int j = 0; j < SEG; ++j) {
        int w = lane * SEG + j;
        float v = vs[SWZ(w)];
        float e = xs[SWZ(w)];
        x = fmaf(v, x - e, e);
        xs[SWZ(w)] = x;
    }
    __syncwarp();

    A = 1.f; B = 0.f;
#pragma unroll
    for (int j = 0; j < SEG; ++j) {
        int w = (WLEN - 1) - (lane * SEG + j);
        float v = (w == WLEN - 1) ? 0.f : vs[SWZ(w + 1)];
        float e = xs[SWZ(w)];
        B = fmaf(v, B - e, e);
        A *= v;
    }
#pragma unroll
    for (int d = 1; d < 32; d <<= 1) {
        float Au = __shfl_up_sync(0xffffffffu, A, d);
        float Bu = __shfl_up_sync(0xffffffffu, B, d);
        if (lane >= d) { B = fmaf(A, Bu, B); A *= Au; }
    }
    c = __shfl_up_sync(0xffffffffu, B, 1);
    x = (lane == 0) ? 0.f : c;
#pragma unroll
    for (int j = 0; j < SEG; ++j) {
        int w = (WLEN - 1) - (lane * SEG + j);
        float v = (w == WLEN - 1) ? 0.f : vs[SWZ(w + 1)];
        float e = xs[SWZ(w)];
        x = fmaf(v, x - e, e);
        xs[SWZ(w)] = x;
    }
    __syncwarp();
}

// ---------------------------------------------------------------------------
// V precompute: V1 = exp(cc0 * (1 + 150*edge)), V2 = V1^2  (sigma0 = 2*sigma1)
__global__ void __launch_bounds__(1024) vprep(const float* __restrict__ edge,
                                              float cc0, int n) {
    int i = blockIdx.x * blockDim.x + threadIdx.x;
    if (i < n) {
        float D  = fmaf(150.f, edge[i], 1.f);
        float v1 = expf(cc0 * D);
        g_V1[i] = v1;
        g_V2[i] = v1 * v1;
    }
}

// ---------------------------------------------------------------------------
// Horizontal pass: 8 warps = 8 channels of one (b,h); coalesced LDG/STG,
// smem transpose, register scan. 18.4 KB smem, 256 threads -> ~5 blocks/SM.
__global__ void __launch_bounds__(256) dt_h(const float* __restrict__ src,
                                            float* __restrict__ dst,
                                            const float* __restrict__ Vg) {
    __shared__ float timg[8 * WLEN];
    __shared__ float vs[WLEN];

    int t = threadIdx.x, lane = t & 31, warp = t >> 5;
    int cg = blockIdx.x & 3;             // channel group: 8 channels each
    int h  = (blockIdx.x >> 2) & 511;
    int b  = blockIdx.x >> 11;

    // stage V row (shared by all 8 channels)
    if (t < 128) {
        float4 vv = reinterpret_cast<const float4*>(Vg + ((size_t)b * 512 + h) * 512)[t];
        int w = 4 * t;
        vs[SWZ(w)]     = vv.x;
        vs[SWZ(w + 1)] = vv.y;
        vs[SWZ(w + 2)] = vv.z;
        vs[SWZ(w + 3)] = vv.w;
    }

    // coalesced load of this warp's line, staged through smem
    size_t base = (((size_t)b * 32 + cg * 8 + warp) * 512 + h) * 512;
    const float4* s4 = reinterpret_cast<const float4*>(src + base);
    float* line = timg + warp * WLEN;
#pragma unroll
    for (int q = 0; q < 4; ++q) {
        float4 d = s4[32 * q + lane];
        int w = 4 * (32 * q + lane);
        line[SWZ(w)]     = d.x;
        line[SWZ(w + 1)] = d.y;
        line[SWZ(w + 2)] = d.z;
        line[SWZ(w + 3)] = d.w;
    }
    __syncthreads();

    // gather lane segment into registers (conflict-free SWZ pattern)
    float x[SEG], v[SEG];
#pragma unroll
    for (int j = 0; j < SEG; ++j) {
        int s = SWZ(SEG * lane + j);
        x[j] = line[s];
        v[j] = vs[s];
    }
    if (lane == 0) v[0] = 0.f;           // boundary: a_0 = 0

    scan_regs(x, v, lane);

#pragma unroll
    for (int j = 0; j < SEG; ++j) line[SWZ(SEG * lane + j)] = x[j];
    __syncwarp();

    // coalesced store
    float4* d4 = reinterpret_cast<float4*>(dst + base);
#pragma unroll
    for (int q = 0; q < 4; ++q) {
        int w = 4 * (32 * q + lane);
        float4 o;
        o.x = line[SWZ(w)];
        o.y = line[SWZ(w + 1)];
        o.z = line[SWZ(w + 2)];
        o.w = line[SWZ(w + 3)];
        d4[32 * q + lane] = o;
    }
}

// ---------------------------------------------------------------------------
// Vertical pass (R3-proven): block = (b, c, 16-column group), 16 warps = 16
// columns, smem scan. 65.8 KB smem, 512 threads -> 3 blocks/SM.
__global__ void __launch_bounds__(512) dt_v(const float* __restrict__ src,
                                            float* __restrict__ dst,
                                            const float* __restrict__ Vg) {
    extern __shared__ float sm[];
    float* timg = sm;                  // 16 * 514
    float* tv   = sm + VCOLS * VSTR;   // 16 * 514

    int t = threadIdx.x, lane = t & 31, warp = t >> 5;
    int wg = blockIdx.x & 31, c = (blockIdx.x >> 5) & 31, b = blockIdx.x >> 10;
    int w0 = wg * VCOLS;
    int f = t & 3, row = t >> 2;       // f: float4 slot along w, row: h sub-row

    const float* sbase = src + (((size_t)b * 32 + c) * 512) * 512 + w0;
    const float* vbase = Vg + ((size_t)b * 512) * 512 + w0;

#pragma unroll
    for (int k = 0; k < 4; ++k) {
        int h = k * 128 + row;
        float4 d  = *reinterpret_cast<const float4*>(sbase + (size_t)h * 512 + f * 4);
        float4 vv = *reinterpret_cast<const float4*>(vbase + (size_t)h * 512 + f * 4);
        if (h == 0) { vv.x = 0.f; vv.y = 0.f; vv.z = 0.f; vv.w = 0.f; }
        int s = SWZ(h);
        int col = f * 4;
        timg[(col    ) * VSTR + s] = d.x;
        timg[(col + 1) * VSTR + s] = d.y;
        timg[(col + 2) * VSTR + s] = d.z;
        timg[(col + 3) * VSTR + s] = d.w;
        tv  [(col    ) * VSTR + s] = vv.x;
        tv  [(col + 1) * VSTR + s] = vv.y;
        tv  [(col + 2) * VSTR + s] = vv.z;
        tv  [(col + 3) * VSTR + s] = vv.w;
    }
    __syncthreads();

    scan_line(timg + warp * VSTR, tv + warp * VSTR, lane);
    __syncthreads();

    float* dbase = dst + (((size_t)b * 32 + c) * 512) * 512 + w0;
#pragma unroll
    for (int k = 0; k < 4; ++k) {
        int h = k * 128 + row;
        int s = SWZ(h);
        int col = f * 4;
        float4 o;
        o.x = timg[(col    ) * VSTR + s];
        o.y = timg[(col + 1) * VSTR + s];
        o.z = timg[(col + 2) * VSTR + s];
        o.w = timg[(col + 3) * VSTR + s];
        *reinterpret_cast<float4*>(dbase + (size_t)h * 512 + f * 4) = o;
    }
}

// ---------------------------------------------------------------------------
extern "C" void kernel_launch(void* const* d_in, const int* in_sizes, int n_in,
                              void* d_out, int out_size) {
    const float* img  = (const float*)d_in[0];
    const float* edge = (const float*)d_in[1];
    if (n_in >= 2 && in_sizes[0] == (1 << 20)) {
        const float* tmp = img; img = edge; edge = tmp;
    }
    float* out = (float*)d_out;

    float *buf, *V1, *V2;
    cudaGetSymbolAddress((void**)&buf, g_buf);
    cudaGetSymbolAddress((void**)&V1, g_V1);
    cudaGetSymbolAddress((void**)&V2, g_V2);

    const int SMEM_V = 2 * VCOLS * VSTR * (int)sizeof(float);       // 65792 B
    cudaFuncSetAttribute(dt_v, cudaFuncAttributeMaxDynamicSharedMemorySize, SMEM_V);

    // sigma_0 = 60*sqrt(3)*2/sqrt(15);  cc0 = -sqrt(2)/sigma_0;  sigma_1 = sigma_0/2
    double sigma0 = 60.0 * 1.7320508075688772 * 2.0 / sqrt(15.0);
    float cc0 = (float)(-1.4142135623730951 / sigma0);

    vprep<<<1024, 1024>>>(edge, cc0, 1 << 20);
    dt_h<<<8192, 256>>>(img, buf, V1);            // iter 0, horizontal
    dt_v<<<4096, 512, SMEM_V>>>(buf, buf, V1);    // iter 0, vertical (in place)
    dt_h<<<8192, 256>>>(buf, buf, V2);            // iter 1, horizontal (in place)
    dt_v<<<4096, 512, SMEM_V>>>(buf, out, V2);    // iter 1, vertical -> output
}

// round 12
// speedup vs baseline: 1.3242x; 1.0550x over previous
#include <cuda_runtime.h>
#include <cmath>

#define WLEN  512
#define SEG   16
#define VCOLS 16
#define VSTR  514   // vertical tile column stride; 514 % 32 == 2 -> conflict-free staging

// Scratch (device globals: allocation-free rule)
__device__ float g_buf[4 * 32 * 512 * 512];   // 128 MB intermediate
__device__ float g_V1[4 * 512 * 512];         // exp(cc0 * D)
__device__ float g_V2[4 * 512 * 512];         // V1^2

__device__ __forceinline__ int SWZ(int w) { return w ^ (w >> 5); }

// ---------------------------------------------------------------------------
// Register-resident forward+backward scan, v[] in registers (dt_h variant).
// Lane l owns elements [16l, 16l+16) in x[]; lane 0's v[0] must be 0.
__device__ __forceinline__ void scan_regs(float x[SEG], float v[SEG], int lane) {
    const unsigned M = 0xffffffffu;

    // ---- forward: x_i = v_i*x_{i-1} + (1-v_i)*e_i, x_{-1} = 0
    float A = 1.f, B = 0.f;
#pragma unroll
    for (int j = 0; j < SEG; ++j) { B = fmaf(v[j], B - x[j], x[j]); A *= v[j]; }
#pragma unroll
    for (int d = 1; d < 32; d <<= 1) {
        float Au = __shfl_up_sync(M, A, d);
        float Bu = __shfl_up_sync(M, B, d);
        if (lane >= d) { B = fmaf(A, Bu, B); A *= Au; }
    }
    float cf = __shfl_up_sync(M, B, 1);
    float xx = (lane == 0) ? 0.f : cf;
#pragma unroll
    for (int j = 0; j < SEG; ++j) { xx = fmaf(v[j], xx - x[j], x[j]); x[j] = xx; }

    // ---- backward: y_i = w_i*y_{i+1} + (1-w_i)*x_i, w_i = v_{i+1}, w_511 = 0
    float w15 = __shfl_down_sync(M, v[0], 1);   // next lane's v[0] = V at 16l+16
    if (lane == 31) w15 = 0.f;
    A = 1.f; B = 0.f;
#pragma unroll
    for (int j = SEG - 1; j >= 0; --j) {
        float w = (j == SEG - 1) ? w15 : v[j + 1];
        B = fmaf(w, B - x[j], x[j]); A *= w;
    }
#pragma unroll
    for (int d = 1; d < 32; d <<= 1) {
        float Ad = __shfl_down_sync(M, A, d);
        float Bd = __shfl_down_sync(M, B, d);
        if (lane + d < 32) { B = fmaf(A, Bd, B); A *= Ad; }
    }
    float cb = __shfl_down_sync(M, B, 1);
    float yy = (lane == 31) ? 0.f : cb;
#pragma unroll
    for (int j = SEG - 1; j >= 0; --j) {
        float w = (j == SEG - 1) ? w15 : v[j + 1];
        yy = fmaf(w, yy - x[j], x[j]);
        x[j] = yy;
    }
}

// ---------------------------------------------------------------------------
// Register-x scan with V read from smem (dt_v variant; lower reg pressure).
// vs is the SWZ-indexed 512-line of V for this warp; vs[SWZ(0)] must be 0.
// v-read pattern SWZ(16l+c), instruction-uniform c in [0,16]: conflict-free.
__device__ __forceinline__ void scan_regs_vsm(float x[SEG], const float* vs, int lane) {
    const unsigned M = 0xffffffffu;

    // ---- forward
    float A = 1.f, B = 0.f;
#pragma unroll
    for (int j = 0; j < SEG; ++j) {
        float v = vs[SWZ(SEG * lane + j)];
        B = fmaf(v, B - x[j], x[j]); A *= v;
    }
#pragma unroll
    for (int d = 1; d < 32; d <<= 1) {
        float Au = __shfl_up_sync(M, A, d);
        float Bu = __shfl_up_sync(M, B, d);
        if (lane >= d) { B = fmaf(A, Bu, B); A *= Au; }
    }
    float cf = __shfl_up_sync(M, B, 1);
    float xx = (lane == 0) ? 0.f : cf;
#pragma unroll
    for (int j = 0; j < SEG; ++j) {
        float v = vs[SWZ(SEG * lane + j)];
        xx = fmaf(v, xx - x[j], x[j]); x[j] = xx;
    }

    // ---- backward: w_i = v_{i+1}, w_511 = 0
    A = 1.f; B = 0.f;
#pragma unroll
    for (int j = SEG - 1; j >= 0; --j) {
        int idx = SEG * lane + j;
        float w = 0.f;
        if (idx < WLEN - 1) w = vs[SWZ(idx + 1)];
        B = fmaf(w, B - x[j], x[j]); A *= w;
    }
#pragma unroll
    for (int d = 1; d < 32; d <<= 1) {
        float Ad = __shfl_down_sync(M, A, d);
        float Bd = __shfl_down_sync(M, B, d);
        if (lane + d < 32) { B = fmaf(A, Bd, B); A *= Ad; }
    }
    float cb = __shfl_down_sync(M, B, 1);
    float yy = (lane == 31) ? 0.f : cb;
#pragma unroll
    for (int j = SEG - 1; j >= 0; --j) {
        int idx = SEG * lane + j;
        float w = 0.f;
        if (idx < WLEN - 1) w = vs[SWZ(idx + 1)];
        yy = fmaf(w, yy - x[j], x[j]);
        x[j] = yy;
    }
}

// ---------------------------------------------------------------------------
// V precompute: V1 = exp(cc0 * (1 + 150*edge)), V2 = V1^2  (sigma0 = 2*sigma1)
__global__ void __launch_bounds__(1024) vprep(const float* __restrict__ edge,
                                              float cc0, int n) {
    int i = blockIdx.x * blockDim.x + threadIdx.x;
    if (i < n) {
        float D  = fmaf(150.f, edge[i], 1.f);
        float v1 = expf(cc0 * D);
        g_V1[i] = v1;
        g_V2[i] = v1 * v1;
    }
}

// ---------------------------------------------------------------------------
// Horizontal pass: 8 warps = 8 channels of one (b,h); coalesced LDG/STG,
// smem transpose, register scan. Reg cap 64 -> 4 blocks/SM.
__global__ void __launch_bounds__(256, 4) dt_h(const float* __restrict__ src,
                                               float* __restrict__ dst,
                                               const float* __restrict__ Vg) {
    __shared__ float timg[8 * WLEN];
    __shared__ float vs[WLEN];

    int t = threadIdx.x, lane = t & 31, warp = t >> 5;
    int cg = blockIdx.x & 3;             // channel group: 8 channels each
    int h  = (blockIdx.x >> 2) & 511;
    int b  = blockIdx.x >> 11;

    // stage V row (shared by all 8 channels)
    if (t < 128) {
        float4 vv = reinterpret_cast<const float4*>(Vg + ((size_t)b * 512 + h) * 512)[t];
        int w = 4 * t;
        vs[SWZ(w)]     = vv.x;
        vs[SWZ(w + 1)] = vv.y;
        vs[SWZ(w + 2)] = vv.z;
        vs[SWZ(w + 3)] = vv.w;
    }

    // coalesced load of this warp's line, staged through smem
    size_t base = (((size_t)b * 32 + cg * 8 + warp) * 512 + h) * 512;
    const float4* s4 = reinterpret_cast<const float4*>(src + base);
    float* line = timg + warp * WLEN;
#pragma unroll
    for (int q = 0; q < 4; ++q) {
        float4 d = s4[32 * q + lane];
        int w = 4 * (32 * q + lane);
        line[SWZ(w)]     = d.x;
        line[SWZ(w + 1)] = d.y;
        line[SWZ(w + 2)] = d.z;
        line[SWZ(w + 3)] = d.w;
    }
    __syncthreads();

    // gather lane segment into registers (conflict-free SWZ pattern)
    float x[SEG], v[SEG];
#pragma unroll
    for (int j = 0; j < SEG; ++j) {
        int s = SWZ(SEG * lane + j);
        x[j] = line[s];
        v[j] = vs[s];
    }
    if (lane == 0) v[0] = 0.f;           // boundary: a_0 = 0

    scan_regs(x, v, lane);

#pragma unroll
    for (int j = 0; j < SEG; ++j) line[SWZ(SEG * lane + j)] = x[j];
    __syncwarp();

    // coalesced store
    float4* d4 = reinterpret_cast<float4*>(dst + base);
#pragma unroll
    for (int q = 0; q < 4; ++q) {
        int w = 4 * (32 * q + lane);
        float4 o;
        o.x = line[SWZ(w)];
        o.y = line[SWZ(w + 1)];
        o.z = line[SWZ(w + 2)];
        o.w = line[SWZ(w + 3)];
        d4[32 * q + lane] = o;
    }
}

// ---------------------------------------------------------------------------
// Vertical pass: block = (b, c, 16-column group), 16 warps = 16 columns.
// Staging as in R3; scan now keeps x in registers (v read from smem),
// cutting smem ops ~13 -> ~8 per element and removing LDS from the serial
// fixup chains. Reg cap 42 -> 3 blocks/SM preserved.
__global__ void __launch_bounds__(512, 3) dt_v(const float* __restrict__ src,
                                               float* __restrict__ dst,
                                               const float* __restrict__ Vg) {
    extern __shared__ float sm[];
    float* timg = sm;                  // 16 * 514
    float* tv   = sm + VCOLS * VSTR;   // 16 * 514

    int t = threadIdx.x, lane = t & 31, warp = t >> 5;
    int wg = blockIdx.x & 31, c = (blockIdx.x >> 5) & 31, b = blockIdx.x >> 10;
    int w0 = wg * VCOLS;
    int f = t & 3, row = t >> 2;       // f: float4 slot along w, row: h sub-row

    const float* sbase = src + (((size_t)b * 32 + c) * 512) * 512 + w0;
    const float* vbase = Vg + ((size_t)b * 512) * 512 + w0;

#pragma unroll
    for (int k = 0; k < 4; ++k) {
        int h = k * 128 + row;
        float4 d  = *reinterpret_cast<const float4*>(sbase + (size_t)h * 512 + f * 4);
        float4 vv = *reinterpret_cast<const float4*>(vbase + (size_t)h * 512 + f * 4);
        if (h == 0) { vv.x = 0.f; vv.y = 0.f; vv.z = 0.f; vv.w = 0.f; }
        int s = SWZ(h);
        int col = f * 4;
        timg[(col    ) * VSTR + s] = d.x;
        timg[(col + 1) * VSTR + s] = d.y;
        timg[(col + 2) * VSTR + s] = d.z;
        timg[(col + 3) * VSTR + s] = d.w;
        tv  [(col    ) * VSTR + s] = vv.x;
        tv  [(col + 1) * VSTR + s] = vv.y;
        tv  [(col + 2) * VSTR + s] = vv.z;
        tv  [(col + 3) * VSTR + s] = vv.w;
    }
    __syncthreads();

    // register-x scan: lane l of warp c owns h = [16l, 16l+16) of column c
    {
        float* colp = timg + warp * VSTR;
        const float* vcol = tv + warp * VSTR;
        float x[SEG];
#pragma unroll
        for (int j = 0; j < SEG; ++j) x[j] = colp[SWZ(SEG * lane + j)];
        scan_regs_vsm(x, vcol, lane);
#pragma unroll
        for (int j = 0; j < SEG; ++j) colp[SWZ(SEG * lane + j)] = x[j];
    }
    __syncthreads();

    float* dbase = dst + (((size_t)b * 32 + c) * 512) * 512 + w0;
#pragma unroll
    for (int k = 0; k < 4; ++k) {
        int h = k * 128 + row;
        int s = SWZ(h);
        int col = f * 4;
        float4 o;
        o.x = timg[(col    ) * VSTR + s];
        o.y = timg[(col + 1) * VSTR + s];
        o.z = timg[(col + 2) * VSTR + s];
        o.w = timg[(col + 3) * VSTR + s];
        *reinterpret_cast<float4*>(dbase + (size_t)h * 512 + f * 4) = o;
    }
}

// ---------------------------------------------------------------------------
extern "C" void kernel_launch(void* const* d_in, const int* in_sizes, int n_in,
                              void* d_out, int out_size) {
    const float* img  = (const float*)d_in[0];
    const float* edge = (const float*)d_in[1];
    if (n_in >= 2 && in_sizes[0] == (1 << 20)) {
        const float* tmp = img; img = edge; edge = tmp;
    }
    float* out = (float*)d_out;

    float *buf, *V1, *V2;
    cudaGetSymbolAddress((void**)&buf, g_buf);
    cudaGetSymbolAddress((void**)&V1, g_V1);
    cudaGetSymbolAddress((void**)&V2, g_V2);

    const int SMEM_V = 2 * VCOLS * VSTR * (int)sizeof(float);       // 65792 B
    cudaFuncSetAttribute(dt_v, cudaFuncAttributeMaxDynamicSharedMemorySize, SMEM_V);

    // sigma_0 = 60*sqrt(3)*2/sqrt(15);  cc0 = -sqrt(2)/sigma_0;  sigma_1 = sigma_0/2
    double sigma0 = 60.0 * 1.7320508075688772 * 2.0 / sqrt(15.0);
    float cc0 = (float)(-1.4142135623730951 / sigma0);

    vprep<<<1024, 1024>>>(edge, cc0, 1 << 20);
    dt_h<<<8192, 256>>>(img, buf, V1);            // iter 0, horizontal
    dt_v<<<4096, 512, SMEM_V>>>(buf, buf, V1);    // iter 0, vertical (in place)
    dt_h<<<8192, 256>>>(buf, buf, V2);            // iter 1, horizontal (in place)
    dt_v<<<4096, 512, SMEM_V>>>(buf, out, V2);    // iter 1, vertical -> output
}